// round 2
// baseline (speedup 1.0000x reference)
#include <cuda_runtime.h>
#include <math.h>

#define N_CODES 16384
#define DDIM 32
#define T_TOK 8192
#define CHUNK 1024
#define NCHUNK 8
#define NSTRIP 128   // N_CODES / 128 code-strips per token

// ---------------- scratch (static __device__, allowed) ----------------
__device__ float  g_zf[T_TOK * DDIM];        // normalized z, token-major
__device__ float  g_zn2[T_TOK];              // sum zf^2 per token
__device__ float  g_en[N_CODES * DDIM];      // normalized embedding
__device__ float  g_en2[N_CODES];            // sum en^2 per code
__device__ float  g_fa[CHUNK * (size_t)N_CODES]; // 64MB: fa = -100*d for current chunk
__device__ float4 g_pm[CHUNK * NSTRIP];      // per (token,strip): m, S, W', dmin
__device__ int    g_pidx[CHUNK * NSTRIP];    // per (token,strip): argmin index
__device__ float  g_lse[T_TOK];
__device__ float  g_sent[T_TOK];             // per-token sample entropy
__device__ int    g_idx[T_TOK];
__device__ float  g_avgpart[16 * N_CODES];   // avg_probs partials (chunk*2+half)
__device__ float  g_vqtok[T_TOK];            // per-token sum (zq-zb)^2

// ---------------- f32x2 packed math (sm_100+) ----------------
#define PACK2(d, lo, hi)  asm("mov.b64 %0, {%1, %2};" : "=l"(d) : "f"(lo), "f"(hi))
#define UNPACK2(lo, hi, s) asm("mov.b64 {%0, %1}, %2;" : "=f"(lo), "=f"(hi) : "l"(s))
#define FMA2(d, a, b, c)  asm("fma.rn.f32x2 %0, %1, %2, %3;" : "=l"(d) : "l"(a), "l"(b), "l"(c))

// ---------------- K0: normalize z (gather from (b,c,h,w)) ----------------
__global__ void znorm_kernel(const float* __restrict__ z) {
    int t = blockIdx.x * 8 + (threadIdx.x >> 5);
    int c = threadIdx.x & 31;
    int b = t >> 8, hw = t & 255;
    float x = z[b * 8192 + c * 256 + hw];
    float s = x * x;
#pragma unroll
    for (int m = 16; m; m >>= 1) s += __shfl_xor_sync(0xffffffffu, s, m);
    float n = sqrtf(s);
    float v = x / fmaxf(n, 1e-12f);
    g_zf[t * DDIM + c] = v;
    float s2 = v * v;
#pragma unroll
    for (int m = 16; m; m >>= 1) s2 += __shfl_xor_sync(0xffffffffu, s2, m);
    if (c == 0) g_zn2[t] = s2;
}

__global__ void enorm_kernel(const float* __restrict__ e) {
    int nrow = blockIdx.x * 8 + (threadIdx.x >> 5);
    int c = threadIdx.x & 31;
    float x = e[nrow * DDIM + c];
    float s = x * x;
#pragma unroll
    for (int m = 16; m; m >>= 1) s += __shfl_xor_sync(0xffffffffu, s, m);
    float n = sqrtf(s);
    float v = x / fmaxf(n, 1e-12f);
    g_en[nrow * DDIM + c] = v;
    float s2 = v * v;
#pragma unroll
    for (int m = 16; m; m >>= 1) s2 += __shfl_xor_sync(0xffffffffu, s2, m);
    if (c == 0) g_en2[nrow] = s2;
}

// ---------------- P1: 128x128 fp32 GEMM tile + fa store + strip stats ----------------
__global__ void __launch_bounds__(256) p1_kernel(int tok0) {
    __shared__ float zs[DDIM][128];   // k-major
    __shared__ float es[DDIM][128];   // k-major
    const int tid = threadIdx.x;
    const int c0 = blockIdx.x * 128;
    const int t0 = tok0 + blockIdx.y * 128;

    const float4* zsrc = (const float4*)(g_zf + (size_t)t0 * DDIM);
    const float4* esrc = (const float4*)(g_en + (size_t)c0 * DDIM);
#pragma unroll
    for (int q = 0; q < 4; q++) {
        int fi = tid + q * 256;
        int row = fi >> 3;
        int col = (fi & 7) << 2;
        float4 v = zsrc[fi];
        zs[col][row] = v.x; zs[col + 1][row] = v.y; zs[col + 2][row] = v.z; zs[col + 3][row] = v.w;
        float4 w = esrc[fi];
        es[col][row] = w.x; es[col + 1][row] = w.y; es[col + 2][row] = w.z; es[col + 3][row] = w.w;
    }
    __syncthreads();

    const int tx = tid & 15, ty = tid >> 4;
    unsigned long long acc[8][4];
#pragma unroll
    for (int i = 0; i < 8; i++)
#pragma unroll
        for (int j = 0; j < 4; j++) acc[i][j] = 0ull;  // (0.f, 0.f)

#pragma unroll 4
    for (int k = 0; k < DDIM; k++) {
        float4 ea = *(const float4*)&es[k][tx * 8];
        float4 eb = *(const float4*)&es[k][tx * 8 + 4];
        float4 za = *(const float4*)&zs[k][ty * 8];
        float4 zb = *(const float4*)&zs[k][ty * 8 + 4];
        unsigned long long ep0, ep1, ep2, ep3;
        PACK2(ep0, ea.x, ea.y); PACK2(ep1, ea.z, ea.w);
        PACK2(ep2, eb.x, eb.y); PACK2(ep3, eb.z, eb.w);
        float zv[8] = {za.x, za.y, za.z, za.w, zb.x, zb.y, zb.z, zb.w};
#pragma unroll
        for (int i = 0; i < 8; i++) {
            unsigned long long zz;
            PACK2(zz, zv[i], zv[i]);
            FMA2(acc[i][0], ep0, zz, acc[i][0]);
            FMA2(acc[i][1], ep1, zz, acc[i][1]);
            FMA2(acc[i][2], ep2, zz, acc[i][2]);
            FMA2(acc[i][3], ep3, zz, acc[i][3]);
        }
    }

    // epilogue: d, fa store, per-strip (m, S, W', dmin, idx)
    float e2v[8];
#pragma unroll
    for (int j = 0; j < 8; j++) e2v[j] = g_en2[c0 + tx * 8 + j];

    for (int i = 0; i < 8; i++) {
        int t = t0 + ty * 8 + i;
        float zi2 = g_zn2[t];
        float fav[8];
        float dmin = 3.4e38f;
        int gidx = 0;
#pragma unroll
        for (int jp = 0; jp < 4; jp++) {
            float lo, hi;
            UNPACK2(lo, hi, acc[i][jp]);
            float d0 = zi2 + e2v[2 * jp]     - 2.0f * lo;
            float d1 = zi2 + e2v[2 * jp + 1] - 2.0f * hi;
            fav[2 * jp]     = -100.0f * d0;
            fav[2 * jp + 1] = -100.0f * d1;
            if (d0 < dmin) { dmin = d0; gidx = c0 + tx * 8 + 2 * jp; }
            if (d1 < dmin) { dmin = d1; gidx = c0 + tx * 8 + 2 * jp + 1; }
        }
        float* fr = g_fa + (size_t)(t - tok0) * N_CODES + c0 + tx * 8;
        *(float4*)fr       = make_float4(fav[0], fav[1], fav[2], fav[3]);
        *(float4*)(fr + 4) = make_float4(fav[4], fav[5], fav[6], fav[7]);

        // strip max (16 lanes share a token row)
        float m = fav[0];
#pragma unroll
        for (int j = 1; j < 8; j++) m = fmaxf(m, fav[j]);
#pragma unroll
        for (int s = 1; s < 16; s <<= 1) m = fmaxf(m, __shfl_xor_sync(0xffffffffu, m, s));
        float S = 0.f, W = 0.f;   // W' = sum (fa-m) e^(fa-m)
#pragma unroll
        for (int j = 0; j < 8; j++) {
            float x = fav[j] - m;
            float e = __expf(x);
            S += e;
            W += x * e;
        }
#pragma unroll
        for (int s = 1; s < 16; s <<= 1) {
            S += __shfl_xor_sync(0xffffffffu, S, s);
            W += __shfl_xor_sync(0xffffffffu, W, s);
        }
#pragma unroll
        for (int s = 1; s < 16; s <<= 1) {
            float od = __shfl_xor_sync(0xffffffffu, dmin, s);
            int   oi = __shfl_xor_sync(0xffffffffu, gidx, s);
            if (od < dmin || (od == dmin && oi < gidx)) { dmin = od; gidx = oi; }
        }
        if (tx == 0) {
            int tl = t - tok0;
            g_pm[(size_t)tl * NSTRIP + blockIdx.x] = make_float4(m, S, W, dmin);
            g_pidx[(size_t)tl * NSTRIP + blockIdx.x] = gidx;
        }
    }
}

// ---------------- merge strips per token -> LSE, sample entropy, argmin ----------------
__global__ void merge_kernel(int tok0) {
    int tl = blockIdx.x * 8 + (threadIdx.x >> 5);
    int lane = threadIdx.x & 31;
    float4 v[4];
    int ix[4];
#pragma unroll
    for (int q = 0; q < 4; q++) {
        v[q]  = g_pm[(size_t)tl * NSTRIP + lane + q * 32];
        ix[q] = g_pidx[(size_t)tl * NSTRIP + lane + q * 32];
    }
    float m = fmaxf(fmaxf(v[0].x, v[1].x), fmaxf(v[2].x, v[3].x));
#pragma unroll
    for (int s = 1; s < 32; s <<= 1) m = fmaxf(m, __shfl_xor_sync(0xffffffffu, m, s));
    float S = 0.f, W = 0.f;
#pragma unroll
    for (int q = 0; q < 4; q++) {
        float dm = v[q].x - m;
        float sc = __expf(dm);
        S += v[q].y * sc;
        W += (v[q].z + dm * v[q].y) * sc;
    }
#pragma unroll
    for (int s = 1; s < 32; s <<= 1) {
        S += __shfl_xor_sync(0xffffffffu, S, s);
        W += __shfl_xor_sync(0xffffffffu, W, s);
    }
    float dmin = v[0].w; int gidx = ix[0];
#pragma unroll
    for (int q = 1; q < 4; q++)
        if (v[q].w < dmin || (v[q].w == dmin && ix[q] < gidx)) { dmin = v[q].w; gidx = ix[q]; }
#pragma unroll
    for (int s = 1; s < 32; s <<= 1) {
        float od = __shfl_xor_sync(0xffffffffu, dmin, s);
        int   oi = __shfl_xor_sync(0xffffffffu, gidx, s);
        if (od < dmin || (od == dmin && oi < gidx)) { dmin = od; gidx = oi; }
    }
    if (lane == 0) {
        int t = tok0 + tl;
        float lS = logf(S);
        g_lse[t]  = m + lS;
        g_sent[t] = lS - W / S;     // = LSE - sum(p*fa), cancellation-safe
        g_idx[t]  = gidx;
    }
}

// ---------------- P2: probs from stored fa -> avg_probs partials ----------------
__global__ void p2_kernel(int tok0, int part0) {
    __shared__ float slse[512];
    int tid = threadIdx.x;
    int c = blockIdx.x * 256 + tid;
    int tl0 = blockIdx.y * 512;
    for (int i = tid; i < 512; i += 256) slse[i] = g_lse[tok0 + tl0 + i];
    __syncthreads();
    float acc = 0.f;
    const float* p = g_fa + (size_t)tl0 * N_CODES + c;
#pragma unroll 8
    for (int t = 0; t < 512; t++)
        acc += __expf(p[(size_t)t * N_CODES] - slse[t]);
    g_avgpart[(size_t)(part0 + blockIdx.y) * N_CODES + c] = acc;
}

// ---------------- quantize: z_q_st output + vq partials ----------------
__global__ void quant_kernel(float* __restrict__ out) {
    int t = blockIdx.x * 8 + (threadIdx.x >> 5);
    int c = threadIdx.x & 31;
    float zb = g_zf[t * DDIM + c];
    float e = g_en[(size_t)g_idx[t] * DDIM + c];
    float o = zb + (e - zb);                 // z_q_st forward value
    int b = t >> 8, hw = t & 255;
    out[b * 8192 + c * 256 + hw] = o;
    float df = e - zb;
    float s = df * df;
#pragma unroll
    for (int m = 16; m; m >>= 1) s += __shfl_xor_sync(0xffffffffu, s, m);
    if (c == 0) g_vqtok[t] = s;
}

// ---------------- final reductions -> 3 loss scalars ----------------
__global__ void final_kernel(float* __restrict__ out, int out_size) {
    __shared__ float red[1024];
    int tid = threadIdx.x;
    float a = 0.f, b = 0.f, cc = 0.f;
    for (int t = tid; t < T_TOK; t += 1024) a += g_vqtok[t];
    for (int t = tid; t < T_TOK; t += 1024) b += g_sent[t];
    for (int n = tid; n < N_CODES; n += 1024) {
        float ap = 0.f;
#pragma unroll
        for (int j = 0; j < 16; j++) ap += g_avgpart[j * N_CODES + n];
        ap *= (1.0f / 8192.0f);
        cc -= ap * logf(ap + 1e-5f);
    }
    red[tid] = a; __syncthreads();
    for (int s = 512; s; s >>= 1) { if (tid < s) red[tid] += red[tid + s]; __syncthreads(); }
    float sumA = red[0]; __syncthreads();
    red[tid] = b; __syncthreads();
    for (int s = 512; s; s >>= 1) { if (tid < s) red[tid] += red[tid + s]; __syncthreads(); }
    float sumB = red[0]; __syncthreads();
    red[tid] = cc; __syncthreads();
    for (int s = 512; s; s >>= 1) { if (tid < s) red[tid] += red[tid + s]; __syncthreads(); }
    float sumC = red[0];
    if (tid == 0) {
        float vq = sumA / 262144.0f;             // mean over 32*16*16*32 elements
        out[out_size - 3] = vq;                  // vq_loss
        out[out_size - 2] = 0.25f * vq;          // commit_loss (BETA * same mean)
        float se = sumB / 8192.0f;               // sample_entropy
        out[out_size - 1] = 0.1f * (se - sumC);  // ENT_RATIO * (sample - avg)
    }
}

// ---------------- launcher ----------------
extern "C" void kernel_launch(void* const* d_in, const int* in_sizes, int n_in,
                              void* d_out, int out_size) {
    const float* z   = (const float*)d_in[0];   // (32,32,16,16) f32
    const float* emb = (const float*)d_in[1];   // (16384,32) f32
    float* out = (float*)d_out;                 // 262144 image + 3 losses

    znorm_kernel<<<T_TOK / 8, 256>>>(z);
    enorm_kernel<<<N_CODES / 8, 256>>>(emb);

    for (int k = 0; k < NCHUNK; k++) {
        int tok0 = k * CHUNK;
        p1_kernel<<<dim3(NSTRIP, CHUNK / 128), 256>>>(tok0);
        merge_kernel<<<CHUNK / 8, 256>>>(tok0);
        p2_kernel<<<dim3(N_CODES / 256, 2), 256>>>(tok0, k * 2);
    }

    quant_kernel<<<T_TOK / 8, 256>>>(out);
    final_kernel<<<1, 1024>>>(out, out_size);
}

// round 3
// speedup vs baseline: 1.9418x; 1.9418x over previous
#include <cuda_runtime.h>
#include <math.h>

#define N_CODES 16384
#define DDIM 32
#define T_TOK 8192
#define NSTRIP 128   // N_CODES / 128 code-strips per token

// ---------------- scratch (static __device__, allowed) ----------------
__device__ float  g_zf[T_TOK * DDIM];              // normalized z, token-major
__device__ float  g_zn2[T_TOK];                    // sum zf^2 per token
__device__ float  g_en[N_CODES * DDIM];            // normalized embedding
__device__ float  g_en2[N_CODES];                  // sum en^2 per code
__device__ float  g_fa[(size_t)T_TOK * N_CODES];   // 512MB: fa = -100*d, full matrix
__device__ float4 g_pm[T_TOK * NSTRIP];            // per (token,strip): m, S, W', dmin
__device__ int    g_pidx[T_TOK * NSTRIP];          // per (token,strip): argmin index
__device__ float  g_lse[T_TOK];
__device__ float  g_sent[T_TOK];                   // per-token sample entropy
__device__ int    g_idx[T_TOK];
__device__ float  g_avgpart[16 * N_CODES];         // avg_probs partials (16 token slabs)
__device__ float  g_vqtok[T_TOK];                  // per-token sum (zq-zb)^2

// ---------------- f32x2 packed math (sm_100+) ----------------
#define PACK2(d, lo, hi)   asm("mov.b64 %0, {%1, %2};" : "=l"(d) : "f"(lo), "f"(hi))
#define UNPACK2(lo, hi, s) asm("mov.b64 {%0, %1}, %2;" : "=f"(lo), "=f"(hi) : "l"(s))
#define FMA2(d, a, b, c)   asm("fma.rn.f32x2 %0, %1, %2, %3;" : "=l"(d) : "l"(a), "l"(b), "l"(c))

// ---------------- K0: normalize z (gather from (b,c,h,w)) ----------------
__global__ void znorm_kernel(const float* __restrict__ z) {
    int t = blockIdx.x * 8 + (threadIdx.x >> 5);
    int c = threadIdx.x & 31;
    int b = t >> 8, hw = t & 255;
    float x = z[b * 8192 + c * 256 + hw];
    float s = x * x;
#pragma unroll
    for (int m = 16; m; m >>= 1) s += __shfl_xor_sync(0xffffffffu, s, m);
    float n = sqrtf(s);
    float v = x / fmaxf(n, 1e-12f);
    g_zf[t * DDIM + c] = v;
    float s2 = v * v;
#pragma unroll
    for (int m = 16; m; m >>= 1) s2 += __shfl_xor_sync(0xffffffffu, s2, m);
    if (c == 0) g_zn2[t] = s2;
}

__global__ void enorm_kernel(const float* __restrict__ e) {
    int nrow = blockIdx.x * 8 + (threadIdx.x >> 5);
    int c = threadIdx.x & 31;
    float x = e[nrow * DDIM + c];
    float s = x * x;
#pragma unroll
    for (int m = 16; m; m >>= 1) s += __shfl_xor_sync(0xffffffffu, s, m);
    float n = sqrtf(s);
    float v = x / fmaxf(n, 1e-12f);
    g_en[nrow * DDIM + c] = v;
    float s2 = v * v;
#pragma unroll
    for (int m = 16; m; m >>= 1) s2 += __shfl_xor_sync(0xffffffffu, s2, m);
    if (c == 0) g_en2[nrow] = s2;
}

// ---------------- P1: 128x128 fp32 GEMM tile + fa store + strip stats ----------------
__global__ void __launch_bounds__(256) p1_kernel() {
    __shared__ float zs[DDIM][128];   // k-major
    __shared__ float es[DDIM][128];   // k-major
    const int tid = threadIdx.x;
    const int c0 = blockIdx.x * 128;
    const int t0 = blockIdx.y * 128;

    const float4* zsrc = (const float4*)(g_zf + (size_t)t0 * DDIM);
    const float4* esrc = (const float4*)(g_en + (size_t)c0 * DDIM);
#pragma unroll
    for (int q = 0; q < 4; q++) {
        int fi = tid + q * 256;
        int row = fi >> 3;
        int col = (fi & 7) << 2;
        float4 v = zsrc[fi];
        zs[col][row] = v.x; zs[col + 1][row] = v.y; zs[col + 2][row] = v.z; zs[col + 3][row] = v.w;
        float4 w = esrc[fi];
        es[col][row] = w.x; es[col + 1][row] = w.y; es[col + 2][row] = w.z; es[col + 3][row] = w.w;
    }
    __syncthreads();

    const int tx = tid & 15, ty = tid >> 4;
    unsigned long long acc[8][4];
#pragma unroll
    for (int i = 0; i < 8; i++)
#pragma unroll
        for (int j = 0; j < 4; j++) acc[i][j] = 0ull;  // (0.f, 0.f)

#pragma unroll 8
    for (int k = 0; k < DDIM; k++) {
        // e operands: float4 == two f32x2 pairs, zero-MOV reinterpret
        ulonglong2 e01 = *(const ulonglong2*)&es[k][tx * 8];
        ulonglong2 e23 = *(const ulonglong2*)&es[k][tx * 8 + 4];
        float4 za  = *(const float4*)&zs[k][ty * 8];
        float4 zb4 = *(const float4*)&zs[k][ty * 8 + 4];
        float zv[8] = {za.x, za.y, za.z, za.w, zb4.x, zb4.y, zb4.z, zb4.w};
#pragma unroll
        for (int i = 0; i < 8; i++) {
            unsigned long long zz;
            PACK2(zz, zv[i], zv[i]);
            FMA2(acc[i][0], e01.x, zz, acc[i][0]);
            FMA2(acc[i][1], e01.y, zz, acc[i][1]);
            FMA2(acc[i][2], e23.x, zz, acc[i][2]);
            FMA2(acc[i][3], e23.y, zz, acc[i][3]);
        }
    }

    // epilogue: d, fa store (streaming), per-strip (m, S, W', dmin, idx)
    float e2v[8];
#pragma unroll
    for (int j = 0; j < 8; j++) e2v[j] = g_en2[c0 + tx * 8 + j];

    for (int i = 0; i < 8; i++) {
        int t = t0 + ty * 8 + i;
        float zi2 = g_zn2[t];
        float fav[8];
        float dmin = 3.4e38f;
        int gidx = 0;
#pragma unroll
        for (int jp = 0; jp < 4; jp++) {
            float lo, hi;
            UNPACK2(lo, hi, acc[i][jp]);
            float d0 = zi2 + e2v[2 * jp]     - 2.0f * lo;
            float d1 = zi2 + e2v[2 * jp + 1] - 2.0f * hi;
            fav[2 * jp]     = -100.0f * d0;
            fav[2 * jp + 1] = -100.0f * d1;
            if (d0 < dmin) { dmin = d0; gidx = c0 + tx * 8 + 2 * jp; }
            if (d1 < dmin) { dmin = d1; gidx = c0 + tx * 8 + 2 * jp + 1; }
        }
        float* fr = g_fa + (size_t)t * N_CODES + c0 + tx * 8;
        __stcs((float4*)fr,       make_float4(fav[0], fav[1], fav[2], fav[3]));
        __stcs((float4*)(fr + 4), make_float4(fav[4], fav[5], fav[6], fav[7]));

        // strip stats (16 lanes share a token row)
        float m = fav[0];
#pragma unroll
        for (int j = 1; j < 8; j++) m = fmaxf(m, fav[j]);
#pragma unroll
        for (int s = 1; s < 16; s <<= 1) m = fmaxf(m, __shfl_xor_sync(0xffffffffu, m, s));
        float S = 0.f, W = 0.f;   // W' = sum (fa-m) e^(fa-m)
#pragma unroll
        for (int j = 0; j < 8; j++) {
            float x = fav[j] - m;
            float e = __expf(x);
            S += e;
            W += x * e;
        }
#pragma unroll
        for (int s = 1; s < 16; s <<= 1) {
            S += __shfl_xor_sync(0xffffffffu, S, s);
            W += __shfl_xor_sync(0xffffffffu, W, s);
        }
#pragma unroll
        for (int s = 1; s < 16; s <<= 1) {
            float od = __shfl_xor_sync(0xffffffffu, dmin, s);
            int   oi = __shfl_xor_sync(0xffffffffu, gidx, s);
            if (od < dmin || (od == dmin && oi < gidx)) { dmin = od; gidx = oi; }
        }
        if (tx == 0) {
            g_pm[(size_t)t * NSTRIP + blockIdx.x] = make_float4(m, S, W, dmin);
            g_pidx[(size_t)t * NSTRIP + blockIdx.x] = gidx;
        }
    }
}

// ---------------- merge strips per token -> LSE, sample entropy, argmin ----------------
__global__ void merge_kernel() {
    int t = blockIdx.x * 8 + (threadIdx.x >> 5);
    int lane = threadIdx.x & 31;
    float4 v[4];
    int ix[4];
#pragma unroll
    for (int q = 0; q < 4; q++) {
        v[q]  = g_pm[(size_t)t * NSTRIP + lane + q * 32];
        ix[q] = g_pidx[(size_t)t * NSTRIP + lane + q * 32];
    }
    float m = fmaxf(fmaxf(v[0].x, v[1].x), fmaxf(v[2].x, v[3].x));
#pragma unroll
    for (int s = 1; s < 32; s <<= 1) m = fmaxf(m, __shfl_xor_sync(0xffffffffu, m, s));
    float S = 0.f, W = 0.f;
#pragma unroll
    for (int q = 0; q < 4; q++) {
        float dm = v[q].x - m;
        float sc = __expf(dm);
        S += v[q].y * sc;
        W += (v[q].z + dm * v[q].y) * sc;
    }
#pragma unroll
    for (int s = 1; s < 32; s <<= 1) {
        S += __shfl_xor_sync(0xffffffffu, S, s);
        W += __shfl_xor_sync(0xffffffffu, W, s);
    }
    float dmin = v[0].w; int gidx = ix[0];
#pragma unroll
    for (int q = 1; q < 4; q++)
        if (v[q].w < dmin || (v[q].w == dmin && ix[q] < gidx)) { dmin = v[q].w; gidx = ix[q]; }
#pragma unroll
    for (int s = 1; s < 32; s <<= 1) {
        float od = __shfl_xor_sync(0xffffffffu, dmin, s);
        int   oi = __shfl_xor_sync(0xffffffffu, gidx, s);
        if (od < dmin || (od == dmin && oi < gidx)) { dmin = od; gidx = oi; }
    }
    if (lane == 0) {
        float lS = logf(S);
        g_lse[t]  = m + lS;
        g_sent[t] = lS - W / S;     // = LSE - sum(p*fa), cancellation-safe
        g_idx[t]  = gidx;
    }
}

// ---------------- P2: probs from stored fa -> avg_probs partials ----------------
__global__ void __launch_bounds__(256) p2_kernel() {
    __shared__ float slse[512];
    int tid = threadIdx.x;
    int c = blockIdx.x * 256 + tid;
    int t0 = blockIdx.y * 512;
    for (int i = tid; i < 512; i += 256) slse[i] = g_lse[t0 + i];
    __syncthreads();
    float a0 = 0.f, a1 = 0.f, a2 = 0.f, a3 = 0.f;
    const float* p = g_fa + (size_t)t0 * N_CODES + c;
#pragma unroll 4
    for (int t = 0; t < 512; t += 4) {
        a0 += __expf(__ldcs(p + (size_t)t * N_CODES)       - slse[t]);
        a1 += __expf(__ldcs(p + (size_t)(t + 1) * N_CODES) - slse[t + 1]);
        a2 += __expf(__ldcs(p + (size_t)(t + 2) * N_CODES) - slse[t + 2]);
        a3 += __expf(__ldcs(p + (size_t)(t + 3) * N_CODES) - slse[t + 3]);
    }
    g_avgpart[(size_t)blockIdx.y * N_CODES + c] = (a0 + a1) + (a2 + a3);
}

// ---------------- quantize: z_q_st output + vq partials ----------------
__global__ void quant_kernel(float* __restrict__ out) {
    int t = blockIdx.x * 8 + (threadIdx.x >> 5);
    int c = threadIdx.x & 31;
    float zb = g_zf[t * DDIM + c];
    float e = g_en[(size_t)g_idx[t] * DDIM + c];
    float o = zb + (e - zb);                 // z_q_st forward value
    int b = t >> 8, hw = t & 255;
    out[b * 8192 + c * 256 + hw] = o;
    float df = e - zb;
    float s = df * df;
#pragma unroll
    for (int m = 16; m; m >>= 1) s += __shfl_xor_sync(0xffffffffu, s, m);
    if (c == 0) g_vqtok[t] = s;
}

// ---------------- final reductions -> 3 loss scalars ----------------
__global__ void final_kernel(float* __restrict__ out, int out_size) {
    __shared__ float red[1024];
    int tid = threadIdx.x;
    float a = 0.f, b = 0.f, cc = 0.f;
    for (int t = tid; t < T_TOK; t += 1024) a += g_vqtok[t];
    for (int t = tid; t < T_TOK; t += 1024) b += g_sent[t];
    for (int n = tid; n < N_CODES; n += 1024) {
        float ap = 0.f;
#pragma unroll
        for (int j = 0; j < 16; j++) ap += g_avgpart[j * N_CODES + n];
        ap *= (1.0f / 8192.0f);
        cc -= ap * logf(ap + 1e-5f);
    }
    red[tid] = a; __syncthreads();
    for (int s = 512; s; s >>= 1) { if (tid < s) red[tid] += red[tid + s]; __syncthreads(); }
    float sumA = red[0]; __syncthreads();
    red[tid] = b; __syncthreads();
    for (int s = 512; s; s >>= 1) { if (tid < s) red[tid] += red[tid + s]; __syncthreads(); }
    float sumB = red[0]; __syncthreads();
    red[tid] = cc; __syncthreads();
    for (int s = 512; s; s >>= 1) { if (tid < s) red[tid] += red[tid + s]; __syncthreads(); }
    float sumC = red[0];
    if (tid == 0) {
        float vq = sumA / 262144.0f;             // mean over 32*16*16*32 elements
        out[out_size - 3] = vq;                  // vq_loss
        out[out_size - 2] = 0.25f * vq;          // commit_loss (BETA * same mean)
        float se = sumB / 8192.0f;               // sample_entropy
        out[out_size - 1] = 0.1f * (se - sumC);  // ENT_RATIO * (sample - avg)
    }
}

// ---------------- launcher ----------------
extern "C" void kernel_launch(void* const* d_in, const int* in_sizes, int n_in,
                              void* d_out, int out_size) {
    const float* z   = (const float*)d_in[0];   // (32,32,16,16) f32
    const float* emb = (const float*)d_in[1];   // (16384,32) f32
    float* out = (float*)d_out;                 // 262144 image + 3 losses

    znorm_kernel<<<T_TOK / 8, 256>>>(z);
    enorm_kernel<<<N_CODES / 8, 256>>>(emb);

    p1_kernel<<<dim3(NSTRIP, T_TOK / 128), 256>>>();
    merge_kernel<<<T_TOK / 8, 256>>>();
    p2_kernel<<<dim3(N_CODES / 256, T_TOK / 512), 256>>>();

    quant_kernel<<<T_TOK / 8, 256>>>(out);
    final_kernel<<<1, 1024>>>(out, out_size);
}